// round 17
// baseline (speedup 1.0000x reference)
#include <cuda_runtime.h>
#include <cuda_bf16.h>
#include <cstdint>

#define TT 512
#define BB 64
#define HH 512
#define MM (TT * BB)        // 32768
#define NN (4 * HH)         // 2048
#define GB 16               // batch rows per group
#define GCTAS 32            // CTAs per group

// ---------------- device scratch (static) ----------------
__device__ float g_zx[(size_t)MM * NN];                       // 256 MB, [m][n]
__device__ __nv_bfloat16 g_xhi[(size_t)MM * HH];              // 32 MB
__device__ __nv_bfloat16 g_xlo[(size_t)MM * HH];              // 32 MB
__device__ __nv_bfloat16 g_whi[(size_t)HH * NN];              // 2 MB
__device__ __nv_bfloat16 g_wlo[(size_t)HH * NN];              // 2 MB
__device__ __align__(128) __nv_bfloat16 g_hb[2][2][BB * HH];  // h bf16 planes [buf][hi/lo][b][k]
__device__ int g_flag[1024 * 32];                             // per-WARP epoch flags, 128B stride
__device__ int g_r_u8;

// ---------------- helpers ----------------
static __device__ __forceinline__ float sigf(float x) {
    return __fdividef(1.0f, 1.0f + __expf(-x));
}
static __device__ __forceinline__ float tanhfast(float x) {
    return 2.0f * __fdividef(1.0f, 1.0f + __expf(-2.0f * x)) - 1.0f;
}
static __device__ __forceinline__ float clampf1(float x) { return fminf(fmaxf(x, -1.0f), 1.0f); }
static __device__ __forceinline__ unsigned packbf(float a, float b) {
    __nv_bfloat162 t = __floats2bfloat162_rn(a, b);
    return *(unsigned*)&t;
}
static __device__ __forceinline__ int ld_acq(const int* p) {
    int v;
    asm volatile("ld.acquire.gpu.global.b32 %0,[%1];" : "=r"(v) : "l"(p) : "memory");
    return v;
}
static __device__ __forceinline__ void st_rel(int* p, int v) {
    asm volatile("st.release.gpu.global.b32 [%0],%1;" :: "l"(p), "r"(v) : "memory");
}
static __device__ __forceinline__ void cpa16(uint32_t dst, const void* src) {
    asm volatile("cp.async.cg.shared.global [%0],[%1],16;\n" :: "r"(dst), "l"(src));
}
#define CP_COMMIT() asm volatile("cp.async.commit_group;\n")
#define CP_WAIT(n)  asm volatile("cp.async.wait_group %0;\n" :: "n"(n))

#define LDSM4(R, addr) \
    asm volatile("ldmatrix.sync.aligned.m8n8.x4.shared.b16 {%0,%1,%2,%3},[%4];" \
        : "=r"((R)[0]), "=r"((R)[1]), "=r"((R)[2]), "=r"((R)[3]) : "r"(addr))
#define LDSM2T(R, addr) \
    asm volatile("ldmatrix.sync.aligned.m8n8.x2.trans.shared.b16 {%0,%1},[%2];" \
        : "=r"((R)[0]), "=r"((R)[1]) : "r"(addr))
#define MMA_BF16(C, A, B) \
    asm volatile("mma.sync.aligned.m16n8k16.row.col.f32.bf16.bf16.f32 " \
        "{%0,%1,%2,%3},{%4,%5,%6,%7},{%8,%9},{%0,%1,%2,%3};" \
        : "+f"((C)[0]), "+f"((C)[1]), "+f"((C)[2]), "+f"((C)[3]) \
        : "r"((A)[0]), "r"((A)[1]), "r"((A)[2]), "r"((A)[3]), "r"((B)[0]), "r"((B)[1]))

// ---------------- kernel 1: reset-dtype detection + flag reset ----------------
__global__ void k_detect(const unsigned char* __restrict__ r) {
    __shared__ int nz;
    if (threadIdx.x == 0) nz = 0;
    __syncthreads();
    for (int i = threadIdx.x; i < 1024 * 32; i += blockDim.x) g_flag[i] = 0;
    int loc = 0;
    for (int i = threadIdx.x; i < TT * BB; i += blockDim.x)
        if ((i & 3) && r[i]) loc = 1;
    if (loc) atomicOr(&nz, 1);
    __syncthreads();
    if (threadIdx.x == 0) g_r_u8 = nz;
}

// ---------------- kernel 2: fused prep (convert x, convert Wi, init h) ----------------
__global__ void k_prep(const float* __restrict__ xs, const float* __restrict__ Wi,
                       const float* __restrict__ h0, const void* __restrict__ resets) {
    const int bid = blockIdx.x;
    if (bid < 16384) {
        size_t i0 = ((size_t)bid * blockDim.x + threadIdx.x) * 4;
        #pragma unroll
        for (int u = 0; u < 4; ++u) {
            size_t i = i0 + u;
            if (i < (size_t)MM * HH) {
                float v = xs[i];
                __nv_bfloat16 hi = __float2bfloat16(v);
                g_xhi[i] = hi;
                g_xlo[i] = __float2bfloat16(v - __bfloat162float(hi));
            }
        }
    } else if (bid < 17408) {
        size_t i0 = ((size_t)(bid - 16384) * blockDim.x + threadIdx.x) * 4;
        #pragma unroll
        for (int u = 0; u < 4; ++u) {
            size_t i = i0 + u;
            if (i < (size_t)HH * NN) {
                float v = Wi[i];
                __nv_bfloat16 hi = __float2bfloat16(v);
                g_whi[i] = hi;
                g_wlo[i] = __float2bfloat16(v - __bfloat162float(hi));
            }
        }
    } else {
        const int ru8 = g_r_u8;
        const unsigned char* r8 = (const unsigned char*)resets;
        const int* r32 = (const int*)resets;
        for (int idx = threadIdx.x + (bid - 17408) * blockDim.x; idx < HH * BB;
             idx += 32 * blockDim.x) {
            int b = idx >> 9, k = idx & 511;
            bool rs = ru8 ? (r8[b] != 0) : (r32[b] != 0);
            float hv = rs ? 0.0f : h0[b * HH + k];
            __nv_bfloat16 hi = __float2bfloat16(hv);
            g_hb[0][0][idx] = hi;
            g_hb[0][1][idx] = __float2bfloat16(hv - __bfloat162float(hi));
        }
    }
}

// ---------------- kernel 3: zx = x @ Wi  (bf16 3-split tensor-core GEMM) ----------------
#define AROW 24
#define BROW 136

#define LOAD_STAGE(buf, ks) do {                                                           \
    const int kb_ = (ks) * 16;                                                             \
    _Pragma("unroll")                                                                      \
    for (int j_ = 0; j_ < 4; ++j_) {                                                       \
        int id_ = tid + 256 * j_;                                                          \
        if (id_ < 512) {                                                                   \
            int plane_ = id_ >> 8; int r_ = id_ & 255; int row_ = r_ >> 1; int half_ = r_ & 1; \
            const __nv_bfloat16* src_ = (plane_ ? g_xlo : g_xhi)                           \
                + (size_t)(mbase + row_) * HH + kb_ + half_ * 8;                           \
            uint32_t dst_ = Abase + (((buf) * 2 + plane_) * 128 * AROW + row_ * AROW + half_ * 8) * 2; \
            cpa16(dst_, src_);                                                             \
        } else {                                                                           \
            int id2_ = id_ - 512; int plane_ = id2_ >> 8; int r_ = id2_ & 255;             \
            int krow_ = r_ >> 4; int seg_ = r_ & 15;                                       \
            const __nv_bfloat16* src_ = (plane_ ? g_wlo : g_whi)                           \
                + (size_t)(kb_ + krow_) * NN + nbase + seg_ * 8;                           \
            uint32_t dst_ = Bbase + (((buf) * 2 + plane_) * 16 * BROW + krow_ * BROW + seg_ * 8) * 2; \
            cpa16(dst_, src_);                                                             \
        }                                                                                  \
    } } while (0)

__global__ __launch_bounds__(256) void k_mm_pre() {
    __shared__ __align__(128) __nv_bfloat16 Asm[2][2][128 * AROW];
    __shared__ __align__(128) __nv_bfloat16 Bsm[2][2][16 * BROW];
    const int tid = threadIdx.x;
    const int nbase = blockIdx.x * 128;
    const int mbase = blockIdx.y * 128;
    const int wid = tid >> 5, lane = tid & 31;
    const int wm = wid & 1, wn = wid >> 1;

    uint32_t Abase = (uint32_t)__cvta_generic_to_shared(&Asm[0][0][0]);
    uint32_t Bbase = (uint32_t)__cvta_generic_to_shared(&Bsm[0][0][0]);

    const int gid = lane >> 2, tig = lane & 3;
    const int arow = (lane & 7) + 8 * ((lane >> 3) & 1);
    const int acol = (lane >> 4) * 8;
    const int bk = lane & 15;

    float c[4][4][4] = {};

    LOAD_STAGE(0, 0);
    CP_COMMIT();

    #pragma unroll 1
    for (int ks = 0; ks < 32; ++ks) {
        const int buf = ks & 1;
        if (ks < 31) {
            LOAD_STAGE((ks + 1) & 1, ks + 1);
            CP_COMMIT();
            CP_WAIT(1);
        } else {
            CP_WAIT(0);
        }
        __syncthreads();

        uint32_t a_hi[4][4], a_lo[4][4];
        #pragma unroll
        for (int mi = 0; mi < 4; ++mi) {
            int rowoff = wm * 64 + mi * 16 + arow;
            uint32_t ah = Abase + ((buf * 2 + 0) * 128 * AROW + rowoff * AROW + acol) * 2;
            uint32_t al = Abase + ((buf * 2 + 1) * 128 * AROW + rowoff * AROW + acol) * 2;
            LDSM4(a_hi[mi], ah);
            LDSM4(a_lo[mi], al);
        }
        uint32_t bhf[4][2], blf[4][2];
        #pragma unroll
        for (int ni = 0; ni < 4; ++ni) {
            int n0 = wn * 32 + ni * 8;
            uint32_t bh = Bbase + ((buf * 2 + 0) * 16 * BROW + bk * BROW + n0) * 2;
            uint32_t bl = Bbase + ((buf * 2 + 1) * 16 * BROW + bk * BROW + n0) * 2;
            LDSM2T(bhf[ni], bh);
            LDSM2T(blf[ni], bl);
        }
        #pragma unroll
        for (int mi = 0; mi < 4; ++mi)
            #pragma unroll
            for (int ni = 0; ni < 4; ++ni) {
                MMA_BF16(c[mi][ni], a_hi[mi], bhf[ni]);
                MMA_BF16(c[mi][ni], a_hi[mi], blf[ni]);
                MMA_BF16(c[mi][ni], a_lo[mi], bhf[ni]);
            }
        __syncthreads();
    }

    #pragma unroll
    for (int mi = 0; mi < 4; ++mi)
        #pragma unroll
        for (int ni = 0; ni < 4; ++ni) {
            int m0 = mbase + wm * 64 + mi * 16 + gid;
            int n = nbase + wn * 32 + ni * 8 + tig * 2;
            *(float2*)(g_zx + (size_t)m0 * NN + n) = make_float2(c[mi][ni][0], c[mi][ni][1]);
            *(float2*)(g_zx + (size_t)(m0 + 8) * NN + n) = make_float2(c[mi][ni][2], c[mi][ni][3]);
        }
}

// ---------------- kernel 4: persistent scanned-LSTM, column-split full-K warps ----------------
// 128 CTAs. Group g = cta>>5 owns batch rows [16g,16g+16). CTA lc = cta&31 owns state
// cols [16lc,16lc+16). Warp w owns state cols {16lc+2w, +1} x 4 gates = 8 z-cols, FULL
// K=512 -> no k-split reduction, no zs buffer. Staging: warp w stages h k-slice
// [64w,64w+64) (both planes) into hsm; one __syncthreads; all warps ldmatrix over all k.
// Acc fragment n-col mapping: n -> state s = n>>2, gate g = n&3 (gather-mapped B frags).
// Epilogue: 2x shfl_xor(1) gives each lane all 4 gates of one (row, col). Per-warp
// publish: warp stores its 2 cols x 16 rows of h, __syncwarp, lane0 st.release.
// Producers of k-slice [64w,64w+64): CTAs (grp, 4w..4w+4), all 8 warps -> same 32
// per-warp flags as before, one per lane.
#define HROW 520                          // bf16 per SMEM h row (1040 B)
#define HPLANE (GB * HROW)                // one plane (16 rows)
#define HSM_BYTES (2 * HPLANE * 2)        // 33280
#define SMEM_TOTAL HSM_BYTES

__global__ __launch_bounds__(256, 1)
void lstm_main(const float* __restrict__ Wh, const float* __restrict__ bias,
               const float* __restrict__ c0, const void* __restrict__ resets,
               float* __restrict__ ys) {
    extern __shared__ __align__(128) char smem[];
    __nv_bfloat16* hsm = (__nv_bfloat16*)smem;          // [2 planes][16][HROW]
    const uint32_t hb32 = (uint32_t)__cvta_generic_to_shared(hsm);

    const int tid = threadIdx.x;
    const int cta = blockIdx.x;
    const int grp = cta >> 5;          // 0..3
    const int lc  = cta & 31;          // 0..31
    const int wid = tid >> 5, lane = tid & 31;
    const int gid = lane >> 2, tig = lane & 3;
    const int wk = wid * 64;           // staged k-slice base

    const int srow = lane & 15, schunk = lane >> 4;      // stage identity
    const int arow = (lane & 7) + 8 * ((lane >> 3) & 1); // ldmatrix identity
    const int acol = (lane >> 4) * 8;

    // producer warp-flag polled by this lane: CTA grp*32 + 4*wid + (lane>>3), warp lane&7
    const int* pollflag =
        g_flag + ((((grp * GCTAS + wid * 4 + (lane >> 3)) << 3) + (lane & 7)) << 5);
    // this warp's own publish flag
    int* wflag = g_flag + (((cta << 3) + wid) << 5);

    // ---- build register-resident B fragments (8 z-cols, full K=512) ----
    // n = gid: state s = gid>>2, gate = gid&3; gcol = gate*512 + lc*16 + 2*wid + s
    unsigned bh2[32][2], bl2[32][2];
    {
        const int gcol = (gid & 3) * 512 + lc * 16 + 2 * wid + (gid >> 2);
        #pragma unroll
        for (int kt = 0; kt < 32; ++kt) {
            const int k0 = kt * 16 + 2 * tig;
            float f0 = Wh[(size_t)k0 * NN + gcol];
            float f1 = Wh[(size_t)(k0 + 1) * NN + gcol];
            float f2 = Wh[(size_t)(k0 + 8) * NN + gcol];
            float f3 = Wh[(size_t)(k0 + 9) * NN + gcol];
            float h0f = __bfloat162float(__float2bfloat16(f0));
            float h1f = __bfloat162float(__float2bfloat16(f1));
            float h2f = __bfloat162float(__float2bfloat16(f2));
            float h3f = __bfloat162float(__float2bfloat16(f3));
            bh2[kt][0] = packbf(h0f, h1f);
            bh2[kt][1] = packbf(h2f, h3f);
            bl2[kt][0] = packbf(f0 - h0f, f1 - h1f);
            bl2[kt][1] = packbf(f2 - h2f, f3 - h3f);
        }
    }

    // ---- epilogue identity: lane -> one (row, col) element ----
    const int erow = gid + 8 * (tig & 1);               // 0..15
    const int gb = grp * GB + erow;                     // global batch row
    const int jcol = lc * 16 + 2 * wid + (tig >> 1);    // global state col
    float c = c0[gb * HH + jcol];
    const float bi = bias[jcol];
    const float bf = bias[512 + jcol];
    const float bg = bias[1024 + jcol];
    const float bo = bias[1536 + jcol];
    const int ru8 = g_r_u8;
    const unsigned char* r8 = (const unsigned char*)resets;
    const int* r32 = (const int*)resets;

    for (int t = 0; t < TT; ++t) {
        // prefetches (DRAM / L2) — issued before the flag wait to hide latency
        const float* zxr = g_zx + (size_t)(t * BB + gb) * NN + jcol;
        float p0 = __ldcg(zxr);
        float p1 = __ldcg(zxr + 512);
        float p2 = __ldcg(zxr + 1024);
        float p3 = __ldcg(zxr + 1536);
        bool rs  = ru8 ? (__ldg(r8 + t * BB + gb) != 0) : (__ldg(r32 + t * BB + gb) != 0);
        bool rs2 = false;
        if (t + 1 < TT)
            rs2 = ru8 ? (__ldg(r8 + (t + 1) * BB + gb) != 0)
                      : (__ldg(r32 + (t + 1) * BB + gb) != 0);

        // ---- dependency wait: 32 producer warps (4 CTAs x 8 warps) published h[t] ----
        if (t > 0) {
            int v = ld_acq(pollflag);
            unsigned ok = __ballot_sync(0xffffffffu, v >= t);
            while (ok != 0xffffffffu) {
                __nanosleep(32);
                v = ld_acq(pollflag);
                ok = __ballot_sync(0xffffffffu, v >= t);
            }
        }

        const __nv_bfloat16* hhi = g_hb[t & 1][0] + (size_t)grp * GB * HH;
        const __nv_bfloat16* hlo = g_hb[t & 1][1] + (size_t)grp * GB * HH;

        // ---- stage this warp's k-slice (16 rows x 64 k, 2 planes) ----
        #pragma unroll
        for (int i = 0; i < 4; ++i) {
            const int k0 = wk + (schunk + 2 * i) * 8;
            cpa16(hb32 + (srow * HROW + k0) * 2, hhi + srow * HH + k0);
            cpa16(hb32 + (HPLANE + srow * HROW + k0) * 2, hlo + srow * HH + k0);
        }
        CP_COMMIT();
        CP_WAIT(0);
        __syncthreads();   // all slices resident; also CTA-wide join "all producers >= t"

        // ---- full-K MMA: 4 independent accumulator chains ----
        float acc[4][4];
        #pragma unroll
        for (int q = 0; q < 4; ++q)
            #pragma unroll
            for (int j = 0; j < 4; ++j) acc[q][j] = 0.0f;

        #pragma unroll
        for (int kt = 0; kt < 32; ++kt) {
            unsigned ahi[4], alo[4];
            const uint32_t col = (uint32_t)(kt * 16 + acol);
            uint32_t ah = hb32 + (arow * HROW + col) * 2;
            LDSM4(ahi, ah);
            LDSM4(alo, ah + HPLANE * 2);
            float* a = acc[kt & 3];
            MMA_BF16(a, ahi, bh2[kt]);
            MMA_BF16(a, ahi, bl2[kt]);
            MMA_BF16(a, alo, bh2[kt]);
        }

        float z0 = (acc[0][0] + acc[1][0]) + (acc[2][0] + acc[3][0]);
        float z1 = (acc[0][1] + acc[1][1]) + (acc[2][1] + acc[3][1]);
        float z2 = (acc[0][2] + acc[1][2]) + (acc[2][2] + acc[3][2]);
        float z3 = (acc[0][3] + acc[1][3]) + (acc[2][3] + acc[3][3]);

        // ---- in-warp gate exchange: lane <-> lane^1 ----
        // lane (tig even): holds (row gid: g0,g1)=(z0,z1), sends (row gid+8: g0,g1)=(z2,z3)
        // lane (tig odd):  holds (row gid+8: g2,g3)=(z2,z3), sends (row gid: g2,g3)=(z0,z1)
        const bool odd = (tig & 1);
        float sa = odd ? z0 : z2;
        float sb = odd ? z1 : z3;
        float ra = __shfl_xor_sync(0xffffffffu, sa, 1);
        float rb = __shfl_xor_sync(0xffffffffu, sb, 1);
        float zi = (odd ? ra : z0) + p0 + bi;
        float zf = (odd ? rb : z1) + p1 + bf;
        float zg = (odd ? z2 : ra) + p2 + bg;
        float zo = (odd ? z3 : rb) + p3 + bo;

        // ---- gates, state update, h store, per-warp publish, ys store ----
        if (rs) c = 0.0f;
        float iv = sigf(zi);
        float fv = sigf(zf);
        float gv = tanhfast(zg);
        float ov = sigf(zo);
        float ncr = fv * c + iv * gv;
        float nh = ov * tanhfast(ncr);
        c = clampf1(ncr);
        float nhc = clampf1(nh);

        if (t + 1 < TT) {
            float hv = rs2 ? 0.0f : nhc;
            __nv_bfloat16 hi = __float2bfloat16(hv);
            const int nb = (t + 1) & 1;
            g_hb[nb][0][gb * HH + jcol] = hi;
            g_hb[nb][1][gb * HH + jcol] = __float2bfloat16(hv - __bfloat162float(hi));
            __syncwarp();
            if (lane == 0) st_rel(wflag, t + 1);   // cumulative release after syncwarp
        }

        ys[(size_t)t * BB * HH + (size_t)gb * HH + jcol] = nhc;
    }
}

// ---------------- launch ----------------
extern "C" void kernel_launch(void* const* d_in, const int* in_sizes, int n_in,
                              void* d_out, int out_size) {
    const float* xs     = (const float*)d_in[0];
    const void*  resets = d_in[1];
    const float* c0     = (const float*)d_in[2];
    const float* h0     = (const float*)d_in[3];
    const float* Wi     = (const float*)d_in[4];
    const float* Wh     = (const float*)d_in[5];
    const float* bias   = (const float*)d_in[6];
    float* ys = (float*)d_out;

    cudaFuncSetAttribute(lstm_main, cudaFuncAttributeMaxDynamicSharedMemorySize, SMEM_TOTAL);

    k_detect<<<1, 256>>>((const unsigned char*)resets);
    k_prep<<<17440, 256>>>(xs, Wi, h0, resets);
    dim3 gpre(16, 256);
    k_mm_pre<<<gpre, 256>>>();
    lstm_main<<<128, 256, SMEM_TOTAL>>>(Wh, bias, c0, resets, ys);
}